// round 9
// baseline (speedup 1.0000x reference)
#include <cuda_runtime.h>
#include <math.h>

#define NNODES_MAX 100000
#define NEDGES_MAX 1600000
#define IN_DIM 128
#define HID 64
#define KTOT 320   // IN_DIM + 3*HID
#define NCOLS 256  // 4 gates * HID
#define KC 32
#define NCHUNK 10  // KTOT / KC
#define NPB 64
#define GRID_PERSIST 304   // 2 * 152 SMs (GB300); clamped to ntiles at launch
#define SMEM_BYTES (2 * (NPB * KC + KC * NCOLS) * 4)   // 81920

// ---------------- scratch (static device globals; no allocation) ----------------
__device__ __align__(16) float g_deg [NNODES_MAX];
__device__ __align__(16) int   g_cnt [NNODES_MAX];
__device__ __align__(16) int   g_off [NNODES_MAX];
__device__ __align__(16) int   g_cur [NNODES_MAX];
__device__ int g_total;
__device__ int g_tile;
__device__ __align__(16) long long g_pay[NEDGES_MAX];   // {lw(f32)<<32 | src}
__device__ __align__(16) float g_Tx1 [NNODES_MAX * HID];
__device__ __align__(16) float g_Tx2 [NNODES_MAX * HID];
__device__ __align__(16) float g_Wp  [KTOT * NCOLS];
__device__ __align__(16) float g_biasp[NCOLS];

// ---------------- helpers ----------------
__device__ __forceinline__ float sigf(float v) { return 1.0f / (1.0f + expf(-v)); }

__device__ __forceinline__ unsigned long long ffma2(unsigned long long a,
                                                    unsigned long long b,
                                                    unsigned long long c) {
    unsigned long long d;
    asm("fma.rn.f32x2 %0, %1, %2, %3;" : "=l"(d) : "l"(a), "l"(b), "l"(c));
    return d;
}
__device__ __forceinline__ float2 u2f(unsigned long long u) {
    float2 f; asm("mov.b64 {%0,%1}, %2;" : "=f"(f.x), "=f"(f.y) : "l"(u)); return f;
}
__device__ __forceinline__ unsigned long long dup2(float v) {
    unsigned long long r; asm("mov.b64 %0, {%1, %1};" : "=l"(r) : "f"(v)); return r;
}
__device__ __forceinline__ void cp16(void* smem, const void* gmem) {
    unsigned sa = (unsigned)__cvta_generic_to_shared(smem);
    asm volatile("cp.async.cg.shared.global [%0], [%1], 16;" :: "r"(sa), "l"(gmem));
}
#define CP_COMMIT() asm volatile("cp.async.commit_group;" ::: "memory")
#define CP_WAIT0()  asm volatile("cp.async.wait_group 0;"  ::: "memory")

// ---------------- zero scratch + counters ----------------
__global__ void k_zero(int N) {
    int i = blockIdx.x * blockDim.x + threadIdx.x;
    if (i == 0) { g_total = 0; g_tile = 0; }
    if (i < N) { g_deg[i] = 0.0f; g_cnt[i] = 0; }
}

// ---------------- prep (deg + hist) fused with weight pack, split by block ----------------
__global__ void k_preppack(const int* __restrict__ src, const int* __restrict__ dst,
                           const float* __restrict__ ew, int E, int eb,
                           const float* __restrict__ Wx, const float* __restrict__ bg,
                           const float* __restrict__ theta, const float* __restrict__ convb) {
    int b = blockIdx.x;
    if (b < eb) {
        int e = b * 256 + threadIdx.x;
        if (e >= E) return;
        int s = src[e], d = dst[e];
        float w = (s == d) ? 0.0f : ew[e];
        if (w != 0.0f) atomicAdd(&g_deg[s], w);
        atomicAdd(&g_cnt[d], 1);
    } else {
        int idx = (b - eb) * 256 + threadIdx.x;
        if (idx >= KTOT * NCOLS) return;
        int k = idx / NCOLS, j = idx % NCOLS;
        int g = j >> 6, o = j & 63;
        float v;
        if (k < IN_DIM) {
            v = Wx[(g * IN_DIM + k) * HID + o];
        } else {
            int kk = k - IN_DIM;
            v = theta[((g * 3 + kk / HID) * HID + (kk % HID)) * HID + o];
        }
        g_Wp[idx] = v;
        if (idx < NCOLS) g_biasp[idx] = bg[idx] + convb[idx];
    }
}

// ---------------- offsets via atomic base assignment ----------------
__global__ void k_off(int N) {
    int n = blockIdx.x * blockDim.x + threadIdx.x;
    if (n >= N) return;
    int c = g_cnt[n];
    int o = atomicAdd(&g_total, c);
    g_off[n] = o;
    g_cur[n] = o;
}

// ---------------- fill CSR payload {src, lap_w} ----------------
__global__ void k_fill(const int* __restrict__ src, const int* __restrict__ dst,
                       const float* __restrict__ ew, int E) {
    int e = blockIdx.x * blockDim.x + threadIdx.x;
    if (e >= E) return;
    int s = src[e], d = dst[e];
    float w  = (s == d) ? 0.0f : ew[e];
    float ds = g_deg[s], dd = g_deg[d];
    float is = (ds > 0.0f) ? rsqrtf(ds) : 0.0f;
    float id = (dd > 0.0f) ? rsqrtf(dd) : 0.0f;
    float lw = -is * w * id;
    int pos = atomicAdd(&g_cur[d], 1);
    g_pay[pos] = ((long long)(unsigned long long)__float_as_uint(lw) << 32)
                 | (unsigned)s;
}

// ---------------- aggregate: out[n] = sum_j lw_j * z[src_j]  (register acc, MLP=8) ----------------
template <int TX2>
__global__ __launch_bounds__(256) void k_agg(const float4* __restrict__ z,
                                             const float4* __restrict__ hsub,
                                             float4* __restrict__ outb,
                                             int N) {
    int gid = blockIdx.x * blockDim.x + threadIdx.x;
    int n = gid >> 4;
    if (n >= N) return;
    int c = gid & 15;
    int j   = g_off[n];
    int end = j + g_cnt[n];

    float4 acc = make_float4(0.f, 0.f, 0.f, 0.f);
    for (; j + 7 < end; j += 8) {
        long long pp[8];
        #pragma unroll
        for (int u = 0; u < 8; ++u) pp[u] = g_pay[j + u];
        float4 vv[8];
        float  ll[8];
        #pragma unroll
        for (int u = 0; u < 8; ++u) {
            int s = (int)(pp[u] & 0xffffffffLL);
            ll[u] = __uint_as_float((unsigned)((unsigned long long)pp[u] >> 32));
            vv[u] = z[(long)s * 16 + c];
        }
        #pragma unroll
        for (int u = 0; u < 8; ++u) {
            acc.x = fmaf(ll[u], vv[u].x, acc.x);
            acc.y = fmaf(ll[u], vv[u].y, acc.y);
            acc.z = fmaf(ll[u], vv[u].z, acc.z);
            acc.w = fmaf(ll[u], vv[u].w, acc.w);
        }
    }
    for (; j < end; ++j) {
        long long p0 = g_pay[j];
        int   s0 = (int)(p0 & 0xffffffffLL);
        float l0 = __uint_as_float((unsigned)((unsigned long long)p0 >> 32));
        float4 v0 = z[(long)s0 * 16 + c];
        acc.x = fmaf(l0, v0.x, acc.x); acc.y = fmaf(l0, v0.y, acc.y);
        acc.z = fmaf(l0, v0.z, acc.z); acc.w = fmaf(l0, v0.w, acc.w);
    }
    if (TX2) {
        float4 hv = hsub[(long)n * 16 + c];
        acc.x = 2.0f * acc.x - hv.x; acc.y = 2.0f * acc.y - hv.y;
        acc.z = 2.0f * acc.z - hv.z; acc.w = 2.0f * acc.w - hv.w;
    }
    outb[(long)n * 16 + c] = acc;
}

// ---------------- fused GEMM, persistent tiles, KC=32 double-buffered ----------------
__global__ __launch_bounds__(256, 2) void k_fused(
    const float* __restrict__ x, const float* __restrict__ h,
    const float* __restrict__ tx1, const float* __restrict__ tx2,
    const float* __restrict__ c, const float* __restrict__ Wl,
    const float* __restrict__ bl, float* __restrict__ out, int N, int ntiles) {

    extern __shared__ __align__(16) float sm[];
    float* Xs0 = sm;                 // 2048 floats
    float* Xs1 = sm + NPB * KC;      // 2048
    float* Wsb = sm + 2 * NPB * KC;  // 2 x 8192
    __shared__ int s_tile;

    const int tid = threadIdx.x;
    const int p  = tid & 31;
    const int ty = tid >> 5;
    const int xn  = tid >> 2;
    const int xq0 = (tid & 3) * 2;

    unsigned long long bini[4];
    #pragma unroll
    for (int g = 0; g < 4; ++g)
        bini[g] = *reinterpret_cast<const unsigned long long*>(&g_biasp[g * 64 + 2 * p]);
    unsigned long long blv = *reinterpret_cast<const unsigned long long*>(bl + 2 * p);

    for (;;) {
        if (tid == 0) s_tile = atomicAdd(&g_tile, 1);
        __syncthreads();
        const int tile = s_tile;
        if (tile >= ntiles) break;
        const int nb = tile * NPB;
        const int gxn = nb + xn;

        unsigned long long acc[8][4];
        #pragma unroll
        for (int i = 0; i < 8; ++i)
            #pragma unroll
            for (int g = 0; g < 4; ++g) acc[i][g] = bini[g];

        auto load_x = [&](int kc, float4& a, float4& b) {
            const float* sp; int ld, col;
            if (kc < 4)      { sp = x;   ld = IN_DIM; col = kc * KC; }
            else if (kc < 6) { sp = h;   ld = HID;    col = (kc - 4) * KC; }
            else if (kc < 8) { sp = tx1; ld = HID;    col = (kc - 6) * KC; }
            else             { sp = tx2; ld = HID;    col = (kc - 8) * KC; }
            if (gxn < N) {
                const float* base = sp + (long)gxn * ld + col;
                a = *reinterpret_cast<const float4*>(base + xq0 * 4);
                b = *reinterpret_cast<const float4*>(base + xq0 * 4 + 4);
            } else {
                a = make_float4(0.f, 0.f, 0.f, 0.f);
                b = a;
            }
        };
        auto store_x = [&](int buf, float4 a, float4 b) {
            float* X = buf ? Xs1 : Xs0;
            *reinterpret_cast<float4*>(&X[xn * KC + xq0 * 4])     = a;
            *reinterpret_cast<float4*>(&X[xn * KC + xq0 * 4 + 4]) = b;
        };
        auto issue_w = [&](int kc, int buf) {
            const float4* wp4 = reinterpret_cast<const float4*>(g_Wp + kc * KC * NCOLS);
            float4* ws4 = reinterpret_cast<float4*>(Wsb + buf * (KC * NCOLS));
            #pragma unroll
            for (int r = 0; r < 8; ++r)
                cp16(&ws4[tid + r * 256], &wp4[tid + r * 256]);
            CP_COMMIT();
        };

        issue_w(0, 0);
        {
            float4 a, b; load_x(0, a, b);
            store_x(0, a, b);
        }
        CP_WAIT0();
        __syncthreads();

        for (int kc = 0; kc < NCHUNK; ++kc) {
            const int cur = kc & 1;
            float4 xa, xb;
            if (kc < NCHUNK - 1) {
                issue_w(kc + 1, cur ^ 1);
                load_x(kc + 1, xa, xb);
            }
            {
                const unsigned long long* wr =
                    reinterpret_cast<const unsigned long long*>(Wsb + cur * (KC * NCOLS));
                const float* xf = cur ? Xs1 : Xs0;
                for (int ko = 0; ko < KC; ko += 8) {
                    #pragma unroll
                    for (int k8 = 0; k8 < 8; ++k8) {
                        int kk = ko + k8;
                        unsigned long long a[8], b[4];
                        #pragma unroll
                        for (int i = 0; i < 8; ++i) a[i] = dup2(xf[(ty + 8 * i) * KC + kk]);
                        #pragma unroll
                        for (int g = 0; g < 4; ++g) b[g] = wr[kk * 128 + g * 32 + p];
                        #pragma unroll
                        for (int i = 0; i < 8; ++i)
                            #pragma unroll
                            for (int g = 0; g < 4; ++g) acc[i][g] = ffma2(a[i], b[g], acc[i][g]);
                    }
                }
            }
            if (kc < NCHUNK - 1)
                store_x(cur ^ 1, xa, xb);
            CP_WAIT0();
            __syncthreads();
        }

        // ---- gates + h0/c0 + relu(h0)@Wl + bl (reuse smem) ----
        float* Hs  = sm;          // [64][64]
        float* Wls = sm + 4096;   // [64][64]

        #pragma unroll
        for (int i = 0; i < 8; ++i) {
            int nl = ty + 8 * i;
            int n = nb + nl;
            float2 pi = u2f(acc[i][0]);
            float2 pf = u2f(acc[i][1]);
            float2 pt = u2f(acc[i][2]);
            float2 po = u2f(acc[i][3]);
            float r0 = 0.0f, r1 = 0.0f;
            if (n < N) {
                float2 cold = *reinterpret_cast<const float2*>(c + (long)n * HID + 2 * p);
                float ig0 = sigf(pi.x), ig1 = sigf(pi.y);
                float fg0 = sigf(pf.x), fg1 = sigf(pf.y);
                float tg0 = tanhf(pt.x), tg1 = tanhf(pt.y);
                float og0 = sigf(po.x), og1 = sigf(po.y);
                float c00 = fg0 * cold.x + ig0 * tg0;
                float c01 = fg1 * cold.y + ig1 * tg1;
                float h00 = og0 * tanhf(c00);
                float h01 = og1 * tanhf(c01);
                *reinterpret_cast<float2*>(out + (long)N * HID + (long)n * HID + 2 * p)
                    = make_float2(h00, h01);
                *reinterpret_cast<float2*>(out + 2L * N * HID + (long)n * HID + 2 * p)
                    = make_float2(c00, c01);
                r0 = fmaxf(h00, 0.0f);
                r1 = fmaxf(h01, 0.0f);
            }
            Hs[nl * 64 + 2 * p]     = r0;
            Hs[nl * 64 + 2 * p + 1] = r1;
        }
        {
            float4* wl4 = reinterpret_cast<float4*>(Wls);
            const float4* wlg = reinterpret_cast<const float4*>(Wl);
            #pragma unroll
            for (int r = 0; r < 4; ++r) wl4[tid + r * 256] = wlg[tid + r * 256];
        }
        __syncthreads();

        float o0[8], o1[8];
        #pragma unroll
        for (int i = 0; i < 8; ++i) {
            float2 b2 = u2f(blv);
            o0[i] = b2.x; o1[i] = b2.y;
        }
        for (int k = 0; k < 64; ++k) {
            float2 w = *reinterpret_cast<const float2*>(Wls + k * 64 + 2 * p);
            #pragma unroll
            for (int i = 0; i < 8; ++i) {
                float a = Hs[(ty + 8 * i) * 64 + k];
                o0[i] = fmaf(a, w.x, o0[i]);
                o1[i] = fmaf(a, w.y, o1[i]);
            }
        }
        #pragma unroll
        for (int i = 0; i < 8; ++i) {
            int n = nb + ty + 8 * i;
            if (n < N)
                *reinterpret_cast<float2*>(out + (long)n * HID + 2 * p)
                    = make_float2(o0[i], o1[i]);
        }
        __syncthreads();   // smem (Hs/Wls) dead before next tile's prologue writes
    }
}

// ---------------- launch ----------------
extern "C" void kernel_launch(void* const* d_in, const int* in_sizes, int n_in,
                              void* d_out, int out_size) {
    const float* x   = (const float*)d_in[0];
    const int*   ei  = (const int*)d_in[1];
    const float* ew  = (const float*)d_in[2];
    const float* h   = (const float*)d_in[3];
    const float* c   = (const float*)d_in[4];
    const float* Wx  = (const float*)d_in[5];
    const float* bg  = (const float*)d_in[6];
    const float* th  = (const float*)d_in[7];
    const float* cb  = (const float*)d_in[8];
    const float* Wl  = (const float*)d_in[9];
    const float* bl  = (const float*)d_in[10];
    float* out = (float*)d_out;

    const int N = in_sizes[0] / IN_DIM;
    const int E = in_sizes[1] / 2;
    const int* src = ei;
    const int* dst = ei + E;

    void *p_tx1, *p_tx2;
    cudaGetSymbolAddress(&p_tx1, g_Tx1);
    cudaGetSymbolAddress(&p_tx2, g_Tx2);

    static int smem_set = 0;
    if (!smem_set) {
        cudaFuncSetAttribute(k_fused, cudaFuncAttributeMaxDynamicSharedMemorySize,
                             SMEM_BYTES);
        smem_set = 1;
    }

    const int eb = (E + 255) / 256;
    const int pb = (KTOT * NCOLS + 255) / 256;
    const int ntiles = (N + NPB - 1) / NPB;

    k_zero<<<(N + 255) / 256, 256>>>(N);
    k_preppack<<<eb + pb, 256>>>(src, dst, ew, E, eb, Wx, bg, th, cb);
    k_off<<<(N + 255) / 256, 256>>>(N);
    k_fill<<<eb, 256>>>(src, dst, ew, E);

    const int ab = (N * 16 + 255) / 256;
    k_agg<0><<<ab, 256>>>((const float4*)h, nullptr, (float4*)p_tx1, N);
    k_agg<1><<<ab, 256>>>((const float4*)p_tx1, (const float4*)h, (float4*)p_tx2, N);

    int grid = GRID_PERSIST;
    if (grid > ntiles) grid = ntiles;
    k_fused<<<grid, 256, SMEM_BYTES>>>(x, h, (const float*)p_tx1, (const float*)p_tx2,
                                       c, Wl, bl, out, N, ntiles);
}

// round 10
// speedup vs baseline: 1.1411x; 1.1411x over previous
#include <cuda_runtime.h>
#include <math.h>

#define NNODES_MAX 100000
#define NEDGES_MAX 1600000
#define IN_DIM 128
#define HID 64
#define KTOT 320   // IN_DIM + 3*HID
#define NCOLS 256  // 4 gates * HID
#define KC 32
#define NCHUNK 10  // KTOT / KC
#define NPB 64
#define SCAN_BS 256
#define MAX_SBLK 512
#define SMEM_BYTES (2 * (NPB * KC + KC * NCOLS) * 4)   // 81920

// ---------------- scratch (static device globals; no allocation) ----------------
__device__ __align__(16) float g_deg [NNODES_MAX];
__device__ __align__(16) int   g_cnt [NNODES_MAX];
__device__ __align__(16) int   g_off [NNODES_MAX];
__device__ __align__(16) int   g_cur [NNODES_MAX];
__device__ __align__(16) int   g_bsum[MAX_SBLK];
__device__ __align__(16) long long g_pay[NEDGES_MAX];   // {lw(f32)<<32 | src}
__device__ __align__(16) float g_Tx1 [NNODES_MAX * HID];
__device__ __align__(16) float g_Tx2 [NNODES_MAX * HID];
__device__ __align__(16) float g_Wp  [KTOT * NCOLS];
__device__ __align__(16) float g_biasp[NCOLS];

// ---------------- helpers ----------------
__device__ __forceinline__ float sigf(float v) { return 1.0f / (1.0f + expf(-v)); }

__device__ __forceinline__ unsigned long long ffma2(unsigned long long a,
                                                    unsigned long long b,
                                                    unsigned long long c) {
    unsigned long long d;
    asm("fma.rn.f32x2 %0, %1, %2, %3;" : "=l"(d) : "l"(a), "l"(b), "l"(c));
    return d;
}
__device__ __forceinline__ float2 u2f(unsigned long long u) {
    float2 f; asm("mov.b64 {%0,%1}, %2;" : "=f"(f.x), "=f"(f.y) : "l"(u)); return f;
}
__device__ __forceinline__ unsigned long long dup2(float v) {
    unsigned long long r; asm("mov.b64 %0, {%1, %1};" : "=l"(r) : "f"(v)); return r;
}
__device__ __forceinline__ void cp16(void* smem, const void* gmem) {
    unsigned sa = (unsigned)__cvta_generic_to_shared(smem);
    asm volatile("cp.async.cg.shared.global [%0], [%1], 16;" :: "r"(sa), "l"(gmem));
}
#define CP_COMMIT() asm volatile("cp.async.commit_group;" ::: "memory")
#define CP_WAIT0()  asm volatile("cp.async.wait_group 0;"  ::: "memory")

// ---------------- zero scratch + counters ----------------
__global__ void k_zero(int N) {
    int i = blockIdx.x * blockDim.x + threadIdx.x;
    if (i < N) { g_deg[i] = 0.0f; g_cnt[i] = 0; }
}

// ---------------- prep (deg + hist) fused with weight pack, split by block ----------------
__global__ void k_preppack(const int* __restrict__ src, const int* __restrict__ dst,
                           const float* __restrict__ ew, int E, int eb,
                           const float* __restrict__ Wx, const float* __restrict__ bg,
                           const float* __restrict__ theta, const float* __restrict__ convb) {
    int b = blockIdx.x;
    if (b < eb) {
        int e = b * 256 + threadIdx.x;
        if (e >= E) return;
        int s = src[e], d = dst[e];
        float w = (s == d) ? 0.0f : ew[e];
        if (w != 0.0f) atomicAdd(&g_deg[s], w);
        atomicAdd(&g_cnt[d], 1);
    } else {
        int idx = (b - eb) * 256 + threadIdx.x;
        if (idx >= KTOT * NCOLS) return;
        int k = idx / NCOLS, j = idx % NCOLS;
        int g = j >> 6, o = j & 63;
        float v;
        if (k < IN_DIM) {
            v = Wx[(g * IN_DIM + k) * HID + o];
        } else {
            int kk = k - IN_DIM;
            v = theta[((g * 3 + kk / HID) * HID + (kk % HID)) * HID + o];
        }
        g_Wp[idx] = v;
        if (idx < NCOLS) g_biasp[idx] = bg[idx] + convb[idx];
    }
}

// ---------------- deterministic exclusive scan of g_cnt -> g_off (node-ordered CSR) ----------------
__global__ void k_scan1(int N) {
    __shared__ int sm[SCAN_BS];
    int t = threadIdx.x;
    int i = blockIdx.x * SCAN_BS + t;
    int v = (i < N) ? g_cnt[i] : 0;
    sm[t] = v; __syncthreads();
    #pragma unroll
    for (int d = 1; d < SCAN_BS; d <<= 1) {
        int u = (t >= d) ? sm[t - d] : 0;
        __syncthreads();
        sm[t] += u;
        __syncthreads();
    }
    if (i < N) g_off[i] = sm[t] - v;
    if (t == SCAN_BS - 1) g_bsum[blockIdx.x] = sm[t];
}
__global__ void k_scan2(int nb) {
    __shared__ int sm[MAX_SBLK];
    int t = threadIdx.x;
    int v = (t < nb) ? g_bsum[t] : 0;
    sm[t] = v; __syncthreads();
    #pragma unroll
    for (int d = 1; d < MAX_SBLK; d <<= 1) {
        int u = (t >= d) ? sm[t - d] : 0;
        __syncthreads();
        sm[t] += u;
        __syncthreads();
    }
    if (t < nb) g_bsum[t] = sm[t] - v;
}
__global__ void k_scan3(int N) {
    int i = blockIdx.x * SCAN_BS + threadIdx.x;
    if (i >= N) return;
    int o = g_off[i] + g_bsum[blockIdx.x];
    g_off[i] = o;
    g_cur[i] = o;
}

// ---------------- fill CSR payload {src, lap_w} ----------------
__global__ void k_fill(const int* __restrict__ src, const int* __restrict__ dst,
                       const float* __restrict__ ew, int E) {
    int e = blockIdx.x * blockDim.x + threadIdx.x;
    if (e >= E) return;
    int s = src[e], d = dst[e];
    float w  = (s == d) ? 0.0f : ew[e];
    float ds = g_deg[s], dd = g_deg[d];
    float is = (ds > 0.0f) ? rsqrtf(ds) : 0.0f;
    float id = (dd > 0.0f) ? rsqrtf(dd) : 0.0f;
    float lw = -is * w * id;
    int pos = atomicAdd(&g_cur[d], 1);
    g_pay[pos] = ((long long)(unsigned long long)__float_as_uint(lw) << 32)
                 | (unsigned)s;
}

// ---------------- aggregate: out[n] = sum_j lw_j * z[src_j]  (register acc, MLP=8) ----------------
template <int TX2>
__global__ __launch_bounds__(256) void k_agg(const float4* __restrict__ z,
                                             const float4* __restrict__ hsub,
                                             float4* __restrict__ outb,
                                             int N) {
    int gid = blockIdx.x * blockDim.x + threadIdx.x;
    int n = gid >> 4;
    if (n >= N) return;
    int c = gid & 15;
    int j   = g_off[n];
    int end = j + g_cnt[n];

    float4 acc = make_float4(0.f, 0.f, 0.f, 0.f);
    for (; j + 7 < end; j += 8) {
        long long pp[8];
        #pragma unroll
        for (int u = 0; u < 8; ++u) pp[u] = g_pay[j + u];
        float4 vv[8];
        float  ll[8];
        #pragma unroll
        for (int u = 0; u < 8; ++u) {
            int s = (int)(pp[u] & 0xffffffffLL);
            ll[u] = __uint_as_float((unsigned)((unsigned long long)pp[u] >> 32));
            vv[u] = z[(long)s * 16 + c];
        }
        #pragma unroll
        for (int u = 0; u < 8; ++u) {
            acc.x = fmaf(ll[u], vv[u].x, acc.x);
            acc.y = fmaf(ll[u], vv[u].y, acc.y);
            acc.z = fmaf(ll[u], vv[u].z, acc.z);
            acc.w = fmaf(ll[u], vv[u].w, acc.w);
        }
    }
    for (; j < end; ++j) {
        long long p0 = g_pay[j];
        int   s0 = (int)(p0 & 0xffffffffLL);
        float l0 = __uint_as_float((unsigned)((unsigned long long)p0 >> 32));
        float4 v0 = z[(long)s0 * 16 + c];
        acc.x = fmaf(l0, v0.x, acc.x); acc.y = fmaf(l0, v0.y, acc.y);
        acc.z = fmaf(l0, v0.z, acc.z); acc.w = fmaf(l0, v0.w, acc.w);
    }
    if (TX2) {
        float4 hv = hsub[(long)n * 16 + c];
        acc.x = 2.0f * acc.x - hv.x; acc.y = 2.0f * acc.y - hv.y;
        acc.z = 2.0f * acc.z - hv.z; acc.w = 2.0f * acc.w - hv.w;
    }
    outb[(long)n * 16 + c] = acc;
}

// ---------------- fused GEMM (320->256), KC=32 double-buffered (R7-proven) ----------------
__global__ __launch_bounds__(256, 2) void k_fused(
    const float* __restrict__ x, const float* __restrict__ h,
    const float* __restrict__ tx1, const float* __restrict__ tx2,
    const float* __restrict__ c, const float* __restrict__ Wl,
    const float* __restrict__ bl, float* __restrict__ out, int N) {

    extern __shared__ __align__(16) float sm[];
    float* Xs0 = sm;                 // 2048 floats
    float* Xs1 = sm + NPB * KC;      // 2048
    float* Wsb = sm + 2 * NPB * KC;  // 2 x 8192

    const int tid = threadIdx.x;
    const int p  = tid & 31;
    const int ty = tid >> 5;
    const int nb = blockIdx.x * NPB;
    const int xn  = tid >> 2;
    const int xq0 = (tid & 3) * 2;
    const int gxn = nb + xn;

    unsigned long long acc[8][4];
    {
        unsigned long long bini[4];
        #pragma unroll
        for (int g = 0; g < 4; ++g)
            bini[g] = *reinterpret_cast<const unsigned long long*>(&g_biasp[g * 64 + 2 * p]);
        #pragma unroll
        for (int i = 0; i < 8; ++i)
            #pragma unroll
            for (int g = 0; g < 4; ++g) acc[i][g] = bini[g];
    }

    auto load_x = [&](int kc, float4& a, float4& b) {
        const float* sp; int ld, col;
        if (kc < 4)      { sp = x;   ld = IN_DIM; col = kc * KC; }
        else if (kc < 6) { sp = h;   ld = HID;    col = (kc - 4) * KC; }
        else if (kc < 8) { sp = tx1; ld = HID;    col = (kc - 6) * KC; }
        else             { sp = tx2; ld = HID;    col = (kc - 8) * KC; }
        if (gxn < N) {
            const float* base = sp + (long)gxn * ld + col;
            a = *reinterpret_cast<const float4*>(base + xq0 * 4);
            b = *reinterpret_cast<const float4*>(base + xq0 * 4 + 4);
        } else {
            a = make_float4(0.f, 0.f, 0.f, 0.f);
            b = a;
        }
    };
    auto store_x = [&](int buf, float4 a, float4 b) {
        float* X = buf ? Xs1 : Xs0;
        *reinterpret_cast<float4*>(&X[xn * KC + xq0 * 4])     = a;
        *reinterpret_cast<float4*>(&X[xn * KC + xq0 * 4 + 4]) = b;
    };
    auto issue_w = [&](int kc, int buf) {
        const float4* wp4 = reinterpret_cast<const float4*>(g_Wp + kc * KC * NCOLS);
        float4* ws4 = reinterpret_cast<float4*>(Wsb + buf * (KC * NCOLS));
        #pragma unroll
        for (int r = 0; r < 8; ++r)
            cp16(&ws4[tid + r * 256], &wp4[tid + r * 256]);
        CP_COMMIT();
    };

    issue_w(0, 0);
    {
        float4 a, b; load_x(0, a, b);
        store_x(0, a, b);
    }
    CP_WAIT0();
    __syncthreads();

    for (int kc = 0; kc < NCHUNK; ++kc) {
        const int cur = kc & 1;
        float4 xa, xb;
        if (kc < NCHUNK - 1) {
            issue_w(kc + 1, cur ^ 1);
            load_x(kc + 1, xa, xb);
        }
        {
            const unsigned long long* wr =
                reinterpret_cast<const unsigned long long*>(Wsb + cur * (KC * NCOLS));
            const float* xf = cur ? Xs1 : Xs0;
            for (int ko = 0; ko < KC; ko += 8) {
                #pragma unroll
                for (int k8 = 0; k8 < 8; ++k8) {
                    int kk = ko + k8;
                    unsigned long long a[8], b[4];
                    #pragma unroll
                    for (int i = 0; i < 8; ++i) a[i] = dup2(xf[(ty + 8 * i) * KC + kk]);
                    #pragma unroll
                    for (int g = 0; g < 4; ++g) b[g] = wr[kk * 128 + g * 32 + p];
                    #pragma unroll
                    for (int i = 0; i < 8; ++i)
                        #pragma unroll
                        for (int g = 0; g < 4; ++g) acc[i][g] = ffma2(a[i], b[g], acc[i][g]);
                }
            }
        }
        if (kc < NCHUNK - 1)
            store_x(cur ^ 1, xa, xb);
        CP_WAIT0();
        __syncthreads();
    }

    // ---- phase 2: gates + h0/c0 + relu(h0)@Wl + bl (reuse smem) ----
    float* Hs  = sm;          // [64][64]
    float* Wls = sm + 4096;   // [64][64]

    #pragma unroll
    for (int i = 0; i < 8; ++i) {
        int nl = ty + 8 * i;
        int n = nb + nl;
        float2 pi = u2f(acc[i][0]);
        float2 pf = u2f(acc[i][1]);
        float2 pt = u2f(acc[i][2]);
        float2 po = u2f(acc[i][3]);
        float r0 = 0.0f, r1 = 0.0f;
        if (n < N) {
            float2 cold = *reinterpret_cast<const float2*>(c + (long)n * HID + 2 * p);
            float ig0 = sigf(pi.x), ig1 = sigf(pi.y);
            float fg0 = sigf(pf.x), fg1 = sigf(pf.y);
            float tg0 = tanhf(pt.x), tg1 = tanhf(pt.y);
            float og0 = sigf(po.x), og1 = sigf(po.y);
            float c00 = fg0 * cold.x + ig0 * tg0;
            float c01 = fg1 * cold.y + ig1 * tg1;
            float h00 = og0 * tanhf(c00);
            float h01 = og1 * tanhf(c01);
            *reinterpret_cast<float2*>(out + (long)N * HID + (long)n * HID + 2 * p)
                = make_float2(h00, h01);
            *reinterpret_cast<float2*>(out + 2L * N * HID + (long)n * HID + 2 * p)
                = make_float2(c00, c01);
            r0 = fmaxf(h00, 0.0f);
            r1 = fmaxf(h01, 0.0f);
        }
        Hs[nl * 64 + 2 * p]     = r0;
        Hs[nl * 64 + 2 * p + 1] = r1;
    }
    {
        float4* wl4 = reinterpret_cast<float4*>(Wls);
        const float4* wlg = reinterpret_cast<const float4*>(Wl);
        #pragma unroll
        for (int r = 0; r < 4; ++r) wl4[tid + r * 256] = wlg[tid + r * 256];
    }
    __syncthreads();

    float o0[8], o1[8];
    {
        float b0 = bl[2 * p], b1 = bl[2 * p + 1];
        #pragma unroll
        for (int i = 0; i < 8; ++i) { o0[i] = b0; o1[i] = b1; }
    }
    for (int k = 0; k < 64; ++k) {
        float2 w = *reinterpret_cast<const float2*>(Wls + k * 64 + 2 * p);
        #pragma unroll
        for (int i = 0; i < 8; ++i) {
            float a = Hs[(ty + 8 * i) * 64 + k];
            o0[i] = fmaf(a, w.x, o0[i]);
            o1[i] = fmaf(a, w.y, o1[i]);
        }
    }
    #pragma unroll
    for (int i = 0; i < 8; ++i) {
        int n = nb + ty + 8 * i;
        if (n < N)
            *reinterpret_cast<float2*>(out + (long)n * HID + 2 * p) = make_float2(o0[i], o1[i]);
    }
}

// ---------------- launch ----------------
extern "C" void kernel_launch(void* const* d_in, const int* in_sizes, int n_in,
                              void* d_out, int out_size) {
    const float* x   = (const float*)d_in[0];
    const int*   ei  = (const int*)d_in[1];
    const float* ew  = (const float*)d_in[2];
    const float* h   = (const float*)d_in[3];
    const float* c   = (const float*)d_in[4];
    const float* Wx  = (const float*)d_in[5];
    const float* bg  = (const float*)d_in[6];
    const float* th  = (const float*)d_in[7];
    const float* cb  = (const float*)d_in[8];
    const float* Wl  = (const float*)d_in[9];
    const float* bl  = (const float*)d_in[10];
    float* out = (float*)d_out;

    const int N = in_sizes[0] / IN_DIM;
    const int E = in_sizes[1] / 2;
    const int* src = ei;
    const int* dst = ei + E;

    void *p_tx1, *p_tx2;
    cudaGetSymbolAddress(&p_tx1, g_Tx1);
    cudaGetSymbolAddress(&p_tx2, g_Tx2);

    static int smem_set = 0;
    if (!smem_set) {
        cudaFuncSetAttribute(k_fused, cudaFuncAttributeMaxDynamicSharedMemorySize,
                             SMEM_BYTES);
        smem_set = 1;
    }

    const int eb = (E + 255) / 256;
    const int pb = (KTOT * NCOLS + 255) / 256;
    const int nb = (N + SCAN_BS - 1) / SCAN_BS;

    k_zero<<<(N + 255) / 256, 256>>>(N);
    k_preppack<<<eb + pb, 256>>>(src, dst, ew, E, eb, Wx, bg, th, cb);
    k_scan1<<<nb, SCAN_BS>>>(N);
    k_scan2<<<1, MAX_SBLK>>>(nb);
    k_scan3<<<nb, SCAN_BS>>>(N);
    k_fill<<<eb, 256>>>(src, dst, ew, E);

    const int ab = (N * 16 + 255) / 256;
    k_agg<0><<<ab, 256>>>((const float4*)h, nullptr, (float4*)p_tx1, N);
    k_agg<1><<<ab, 256>>>((const float4*)p_tx1, (const float4*)h, (float4*)p_tx2, N);

    k_fused<<<(N + NPB - 1) / NPB, 256, SMEM_BYTES>>>(
        x, h, (const float*)p_tx1, (const float*)p_tx2, c, Wl, bl, out, N);
}